// round 10
// baseline (speedup 1.0000x reference)
#include <cuda_runtime.h>
#include <cstdint>

// Problem shape (fixed by the dataset): N=10000, E=160000, IN=OUT=512, TC=256.
#define MAXN   10240
#define MAXE   163840
#define DIMK   512
#define DIMOUT 512
#define DIMTC  256

// Static device scratch (no runtime allocation allowed).
__device__ float g_xw[MAXN * DIMOUT];   // x @ W
__device__ float g_dinv[MAXN];          // rsqrt(deg)
__device__ float g_tb[DIMOUT];          // b + bt + t_emb @ Wt
__device__ int   g_count[MAXN];         // in-degree (excl self loop)
__device__ int   g_rowstart[MAXN + 1];  // CSR row offsets
__device__ int   g_cursor[MAXN];        // fill cursors
__device__ int   g_csr_src[MAXE];       // src node per CSR slot

// ---------------------------------------------------------------------------
// helpers
// ---------------------------------------------------------------------------
__device__ __forceinline__ float to_tf32(float x) {
    uint32_t u;
    asm("cvt.rna.tf32.f32 %0, %1;" : "=r"(u) : "f"(x));
    return __uint_as_float(u);
}

__device__ __forceinline__ void mma_tf32(float* d, const uint32_t* a, const uint32_t* b) {
    asm volatile(
        "mma.sync.aligned.m16n8k8.row.col.f32.tf32.tf32.f32 "
        "{%0,%1,%2,%3}, {%4,%5,%6,%7}, {%8,%9}, {%0,%1,%2,%3};"
        : "+f"(d[0]), "+f"(d[1]), "+f"(d[2]), "+f"(d[3])
        : "r"(a[0]), "r"(a[1]), "r"(a[2]), "r"(a[3]),
          "r"(b[0]), "r"(b[1]));
}

// ---------------------------------------------------------------------------
// K1 (fused): blocks [0,16): tb[j] = b[j]+bt[j]+sum_k t_emb[k]*Wt[k,j]
//             blocks [16,...): count[i] = 0
// ---------------------------------------------------------------------------
__global__ void k_setup(const float* __restrict__ t_emb,
                        const float* __restrict__ Wt,
                        const float* __restrict__ b,
                        const float* __restrict__ bt,
                        float* __restrict__ tb,
                        int* __restrict__ count, int N) {
    if (blockIdx.x < 16) {
        __shared__ float red[8][32];
        int jloc = threadIdx.x & 31;
        int kc   = threadIdx.x >> 5;
        int j    = blockIdx.x * 32 + jloc;
        float acc = 0.0f;
        int k0 = kc * 32;
#pragma unroll
        for (int k = 0; k < 32; k++) {
            acc += t_emb[k0 + k] * Wt[(k0 + k) * DIMOUT + j];
        }
        red[kc][jloc] = acc;
        __syncthreads();
        if (kc == 0) {
            float s = b[j] + bt[j];
#pragma unroll
            for (int q = 0; q < 8; q++) s += red[q][jloc];
            tb[j] = s;
        }
    } else {
        int i = (blockIdx.x - 16) * blockDim.x + threadIdx.x;
        if (i < N) count[i] = 0;
    }
}

// ---------------------------------------------------------------------------
// K2: histogram of dst (edge_index is INT32: src=[0,E), dst=[E,2E))
// ---------------------------------------------------------------------------
__global__ void k_count_edges(const int* __restrict__ ei, int* count, int E) {
    int e = blockIdx.x * blockDim.x + threadIdx.x;
    if (e < E) atomicAdd(&count[ei[E + e]], 1);
}

// ---------------------------------------------------------------------------
// K3: exclusive scan of count -> rowstart[0..N] + cursor copy + dinv
// ---------------------------------------------------------------------------
__global__ __launch_bounds__(1024) void k_scan(const int* __restrict__ count,
                                               int* __restrict__ rowstart,
                                               int* __restrict__ cursor,
                                               float* __restrict__ dinv, int N) {
    __shared__ int part[1024];
    int tid = threadIdx.x;
    int PER = (N + 1023) >> 10;
    int base = tid * PER;
    int s = 0;
    for (int q = 0; q < PER; q++) {
        int idx = base + q;
        s += (idx < N) ? count[idx] : 0;
    }
    part[tid] = s;
    __syncthreads();
    for (int off = 1; off < 1024; off <<= 1) {
        int v = (tid >= off) ? part[tid - off] : 0;
        __syncthreads();
        part[tid] += v;
        __syncthreads();
    }
    int run = (tid > 0) ? part[tid - 1] : 0;
    for (int q = 0; q < PER; q++) {
        int idx = base + q;
        if (idx <= N) {
            rowstart[idx] = run;
            if (idx < N) cursor[idx] = run;
        }
        if (idx < N) {
            int c = count[idx];
            dinv[idx] = rsqrtf((float)c + 1.0f);
            run += c;
        }
    }
}

// ---------------------------------------------------------------------------
// K4: CSR fill: csr_src[pos] = src, pos = cursor[dst]++
// ---------------------------------------------------------------------------
__global__ void k_fill(const int* __restrict__ ei, int* cursor,
                       int* __restrict__ csr_src, int E) {
    int e = blockIdx.x * blockDim.x + threadIdx.x;
    if (e < E) {
        int s = ei[e];
        int d = ei[E + e];
        int pos = atomicAdd(&cursor[d], 1);
        csr_src[pos] = s;
    }
}

// ---------------------------------------------------------------------------
// K5: TF32 tensor-core GEMM  C[N,512] = A[N,512] @ B[512,512]
// 128x128 block tile, 8 warps of 64x32, BK=32, m16n8k8 mma.sync
// Register-prefetch pipeline: next K-tile LDGs issued before compute phase.
// ---------------------------------------------------------------------------
__global__ __launch_bounds__(256) void k_gemm_tf32(const float* __restrict__ A,
                                                   const float* __restrict__ B,
                                                   float* __restrict__ C, int N) {
    __shared__ float As[128 * 36];
    __shared__ float Bs[32 * 136];

    int tid  = threadIdx.x;
    int lane = tid & 31;
    int wid  = tid >> 5;
    int wm   = wid & 1;
    int wn   = wid >> 1;
    int g    = lane >> 2;
    int c    = lane & 3;

    int rowBase = blockIdx.y * 128;
    int colBase = blockIdx.x * 128;

    float acc[4][4][4];
#pragma unroll
    for (int mt = 0; mt < 4; mt++)
#pragma unroll
        for (int nt = 0; nt < 4; nt++)
#pragma unroll
            for (int q = 0; q < 4; q++) acc[mt][nt][q] = 0.0f;

    int ar  = tid >> 3;        // 0..31
    int ac4 = tid & 7;         // 0..7
    int bkr = tid >> 5;        // 0..7
    int bc4 = tid & 31;        // 0..31

    float4 aPre[4], bPre[4];

    // prologue: load k0 = 0 tile
#pragma unroll
    for (int j = 0; j < 4; j++) {
        int grow = rowBase + ar + 32 * j;
        aPre[j] = make_float4(0.f, 0.f, 0.f, 0.f);
        if (grow < N)
            aPre[j] = *reinterpret_cast<const float4*>(&A[(size_t)grow * DIMK + ac4 * 4]);
        bPre[j] = *reinterpret_cast<const float4*>(
            &B[(size_t)(bkr + 8 * j) * DIMOUT + colBase + bc4 * 4]);
    }

    for (int k0 = 0; k0 < DIMK; k0 += 32) {
        // stage current prefetched tile into SMEM (with tf32 rounding)
#pragma unroll
        for (int j = 0; j < 4; j++) {
            float4 v = aPre[j];
            v.x = to_tf32(v.x); v.y = to_tf32(v.y);
            v.z = to_tf32(v.z); v.w = to_tf32(v.w);
            *reinterpret_cast<float4*>(&As[(ar + 32 * j) * 36 + ac4 * 4]) = v;
            float4 w = bPre[j];
            w.x = to_tf32(w.x); w.y = to_tf32(w.y);
            w.z = to_tf32(w.z); w.w = to_tf32(w.w);
            *reinterpret_cast<float4*>(&Bs[(bkr + 8 * j) * 136 + bc4 * 4]) = w;
        }
        __syncthreads();

        // issue next tile's global loads early (latency hidden by compute)
        if (k0 + 32 < DIMK) {
            int kn = k0 + 32;
#pragma unroll
            for (int j = 0; j < 4; j++) {
                int grow = rowBase + ar + 32 * j;
                aPre[j] = make_float4(0.f, 0.f, 0.f, 0.f);
                if (grow < N)
                    aPre[j] = *reinterpret_cast<const float4*>(
                        &A[(size_t)grow * DIMK + kn + ac4 * 4]);
                bPre[j] = *reinterpret_cast<const float4*>(
                    &B[(size_t)(kn + bkr + 8 * j) * DIMOUT + colBase + bc4 * 4]);
            }
        }

        // compute from SMEM
#pragma unroll
        for (int kk = 0; kk < 32; kk += 8) {
            uint32_t afr[4][4];
            uint32_t bfr[4][2];
#pragma unroll
            for (int mt = 0; mt < 4; mt++) {
                int rb = wm * 64 + mt * 16;
                afr[mt][0] = __float_as_uint(As[(rb + g)     * 36 + kk + c]);
                afr[mt][1] = __float_as_uint(As[(rb + g + 8) * 36 + kk + c]);
                afr[mt][2] = __float_as_uint(As[(rb + g)     * 36 + kk + c + 4]);
                afr[mt][3] = __float_as_uint(As[(rb + g + 8) * 36 + kk + c + 4]);
            }
#pragma unroll
            for (int nt = 0; nt < 4; nt++) {
                int nb = wn * 32 + nt * 8;
                bfr[nt][0] = __float_as_uint(Bs[(kk + c)     * 136 + nb + g]);
                bfr[nt][1] = __float_as_uint(Bs[(kk + c + 4) * 136 + nb + g]);
            }
#pragma unroll
            for (int mt = 0; mt < 4; mt++)
#pragma unroll
                for (int nt = 0; nt < 4; nt++)
                    mma_tf32(acc[mt][nt], afr[mt], bfr[nt]);
        }
        if (k0 + 32 < DIMK) __syncthreads();
    }

#pragma unroll
    for (int mt = 0; mt < 4; mt++) {
        int row = rowBase + wm * 64 + mt * 16 + g;
#pragma unroll
        for (int nt = 0; nt < 4; nt++) {
            int col = colBase + wn * 32 + nt * 8 + 2 * c;
            if (row < N)
                *reinterpret_cast<float2*>(&C[(size_t)row * DIMOUT + col]) =
                    make_float2(acc[mt][nt][0], acc[mt][nt][1]);
            if (row + 8 < N)
                *reinterpret_cast<float2*>(&C[(size_t)(row + 8) * DIMOUT + col]) =
                    make_float2(acc[mt][nt][2], acc[mt][nt][3]);
        }
    }
}

// ---------------------------------------------------------------------------
// K6: CSR gather (atomic-free) — fuses self-loop + time bias
// ---------------------------------------------------------------------------
__global__ __launch_bounds__(128) void k_gather(const int* __restrict__ rowstart,
                                                const int* __restrict__ csr_src,
                                                const float* __restrict__ xw,
                                                const float* __restrict__ dinv,
                                                const float* __restrict__ tb,
                                                float* __restrict__ out, int N) {
    int i = blockIdx.x;
    int t = threadIdx.x;
    int start = rowstart[i];
    int end   = rowstart[i + 1];
    float di  = dinv[i];

    float4 acc = *(reinterpret_cast<const float4*>(tb) + t);
    float4 v0  = __ldg(reinterpret_cast<const float4*>(xw + (size_t)i * DIMOUT) + t);
    float wsel = di * di;
    acc.x += wsel * v0.x;
    acc.y += wsel * v0.y;
    acc.z += wsel * v0.z;
    acc.w += wsel * v0.w;

    for (int j = start; j < end; j++) {
        int s   = __ldg(&csr_src[j]);
        float w = di * __ldg(&dinv[s]);
        float4 v = __ldg(reinterpret_cast<const float4*>(xw + (size_t)s * DIMOUT) + t);
        acc.x += w * v.x;
        acc.y += w * v.y;
        acc.z += w * v.z;
        acc.w += w * v.w;
    }
    *(reinterpret_cast<float4*>(out + (size_t)i * DIMOUT) + t) = acc;
}

// ---------------------------------------------------------------------------
// launch
// ---------------------------------------------------------------------------
extern "C" void kernel_launch(void* const* d_in, const int* in_sizes, int n_in,
                              void* d_out, int out_size) {
    const float* x    = (const float*)d_in[0];
    const float* temb = (const float*)d_in[1];
    const int*   ei   = (const int*)d_in[2];   // int32 (JAX x64 disabled)
    const float* W    = (const float*)d_in[3];
    const float* b    = (const float*)d_in[4];
    const float* Wt   = (const float*)d_in[5];
    const float* bt   = (const float*)d_in[6];
    float*       out  = (float*)d_out;

    int N = in_sizes[0] / DIMK;
    int E = in_sizes[2] / 2;

    float* xw;    cudaGetSymbolAddress((void**)&xw,    g_xw);
    float* dinv;  cudaGetSymbolAddress((void**)&dinv,  g_dinv);
    float* tb;    cudaGetSymbolAddress((void**)&tb,    g_tb);
    int* count;   cudaGetSymbolAddress((void**)&count, g_count);
    int* rowst;   cudaGetSymbolAddress((void**)&rowst, g_rowstart);
    int* cursor;  cudaGetSymbolAddress((void**)&cursor,g_cursor);
    int* csrsrc;  cudaGetSymbolAddress((void**)&csrsrc,g_csr_src);

    int zeroBlocks = (N + 255) / 256;
    k_setup<<<16 + zeroBlocks, 256>>>(temb, Wt, b, bt, tb, count, N);
    k_count_edges<<<(E + 255) / 256, 256>>>(ei, count, E);
    k_scan<<<1, 1024>>>(count, rowst, cursor, dinv, N);
    k_fill<<<(E + 255) / 256, 256>>>(ei, cursor, csrsrc, E);

    dim3 gg(DIMOUT / 128, (N + 127) / 128);
    k_gemm_tf32<<<gg, 256>>>(x, W, xw, N);

    k_gather<<<N, 128>>>(rowst, csrsrc, xw, dinv, tb, out, N);
}

// round 11
// speedup vs baseline: 1.0563x; 1.0563x over previous
#include <cuda_runtime.h>
#include <cuda_fp16.h>
#include <cstdint>

// Problem shape (fixed by the dataset): N=10000, E=160000, IN=OUT=512, TC=256.
#define MAXN   10240
#define MAXE   163840
#define DIMK   512
#define DIMOUT 512
#define DIMTC  256

// Static device scratch (no runtime allocation allowed).
__device__ __half g_xw[MAXN * DIMOUT];  // x @ W  (fp16 to halve gather traffic)
__device__ float  g_dinv[MAXN];         // rsqrt(deg)
__device__ float  g_tb[DIMOUT];         // b + bt + t_emb @ Wt
__device__ int    g_count[MAXN];        // in-degree (excl self loop)
__device__ int    g_rowstart[MAXN + 1]; // CSR row offsets
__device__ int    g_cursor[MAXN];       // fill cursors
__device__ int2   g_csr_sw[MAXE];       // {src, weight_bits} per CSR slot

// ---------------------------------------------------------------------------
// helpers
// ---------------------------------------------------------------------------
__device__ __forceinline__ float to_tf32(float x) {
    uint32_t u;
    asm("cvt.rna.tf32.f32 %0, %1;" : "=r"(u) : "f"(x));
    return __uint_as_float(u);
}

__device__ __forceinline__ void mma_tf32(float* d, const uint32_t* a, const uint32_t* b) {
    asm volatile(
        "mma.sync.aligned.m16n8k8.row.col.f32.tf32.tf32.f32 "
        "{%0,%1,%2,%3}, {%4,%5,%6,%7}, {%8,%9}, {%0,%1,%2,%3};"
        : "+f"(d[0]), "+f"(d[1]), "+f"(d[2]), "+f"(d[3])
        : "r"(a[0]), "r"(a[1]), "r"(a[2]), "r"(a[3]),
          "r"(b[0]), "r"(b[1]));
}

// ---------------------------------------------------------------------------
// K1 (fused): blocks [0,16): tb[j] = b[j]+bt[j]+sum_k t_emb[k]*Wt[k,j]
//             blocks [16,...): count[i] = 0
// ---------------------------------------------------------------------------
__global__ void k_setup(const float* __restrict__ t_emb,
                        const float* __restrict__ Wt,
                        const float* __restrict__ b,
                        const float* __restrict__ bt,
                        float* __restrict__ tb,
                        int* __restrict__ count, int N) {
    if (blockIdx.x < 16) {
        __shared__ float red[8][32];
        int jloc = threadIdx.x & 31;
        int kc   = threadIdx.x >> 5;
        int j    = blockIdx.x * 32 + jloc;
        float acc = 0.0f;
        int k0 = kc * 32;
#pragma unroll
        for (int k = 0; k < 32; k++) {
            acc += t_emb[k0 + k] * Wt[(k0 + k) * DIMOUT + j];
        }
        red[kc][jloc] = acc;
        __syncthreads();
        if (kc == 0) {
            float s = b[j] + bt[j];
#pragma unroll
            for (int q = 0; q < 8; q++) s += red[q][jloc];
            tb[j] = s;
        }
    } else {
        int i = (blockIdx.x - 16) * blockDim.x + threadIdx.x;
        if (i < N) count[i] = 0;
    }
}

// ---------------------------------------------------------------------------
// K2: histogram of dst (edge_index is INT32: src=[0,E), dst=[E,2E))
// ---------------------------------------------------------------------------
__global__ void k_count_edges(const int* __restrict__ ei, int* count, int E) {
    int e = blockIdx.x * blockDim.x + threadIdx.x;
    if (e < E) atomicAdd(&count[ei[E + e]], 1);
}

// ---------------------------------------------------------------------------
// K3: exclusive scan of count -> rowstart[0..N] + cursor copy + dinv
// ---------------------------------------------------------------------------
__global__ __launch_bounds__(1024) void k_scan(const int* __restrict__ count,
                                               int* __restrict__ rowstart,
                                               int* __restrict__ cursor,
                                               float* __restrict__ dinv, int N) {
    __shared__ int part[1024];
    int tid = threadIdx.x;
    int PER = (N + 1023) >> 10;
    int base = tid * PER;
    int s = 0;
    for (int q = 0; q < PER; q++) {
        int idx = base + q;
        s += (idx < N) ? count[idx] : 0;
    }
    part[tid] = s;
    __syncthreads();
    for (int off = 1; off < 1024; off <<= 1) {
        int v = (tid >= off) ? part[tid - off] : 0;
        __syncthreads();
        part[tid] += v;
        __syncthreads();
    }
    int run = (tid > 0) ? part[tid - 1] : 0;
    for (int q = 0; q < PER; q++) {
        int idx = base + q;
        if (idx <= N) {
            rowstart[idx] = run;
            if (idx < N) cursor[idx] = run;
        }
        if (idx < N) {
            int c = count[idx];
            dinv[idx] = rsqrtf((float)c + 1.0f);
            run += c;
        }
    }
}

// ---------------------------------------------------------------------------
// K4: CSR fill: csr_sw[pos] = {src, dinv[src]*dinv[dst]}, pos = cursor[dst]++
// (dinv is ready — k_scan runs before this)
// ---------------------------------------------------------------------------
__global__ void k_fill(const int* __restrict__ ei, int* cursor,
                       const float* __restrict__ dinv,
                       int2* __restrict__ csr_sw, int E) {
    int e = blockIdx.x * blockDim.x + threadIdx.x;
    if (e < E) {
        int s = ei[e];
        int d = ei[E + e];
        float w = dinv[s] * dinv[d];
        int pos = atomicAdd(&cursor[d], 1);
        csr_sw[pos] = make_int2(s, __float_as_int(w));
    }
}

// ---------------------------------------------------------------------------
// K5: TF32 tensor-core GEMM  C[N,512] = A[N,512] @ B[512,512], fp16 output
// 128x128 block tile, 8 warps of 64x32, BK=32, m16n8k8 mma.sync
// ---------------------------------------------------------------------------
__global__ __launch_bounds__(256) void k_gemm_tf32(const float* __restrict__ A,
                                                   const float* __restrict__ B,
                                                   __half* __restrict__ C, int N) {
    __shared__ float As[128 * 36];
    __shared__ float Bs[32 * 136];

    int tid  = threadIdx.x;
    int lane = tid & 31;
    int wid  = tid >> 5;
    int wm   = wid & 1;
    int wn   = wid >> 1;
    int g    = lane >> 2;
    int c    = lane & 3;

    int rowBase = blockIdx.y * 128;
    int colBase = blockIdx.x * 128;

    float acc[4][4][4];
#pragma unroll
    for (int mt = 0; mt < 4; mt++)
#pragma unroll
        for (int nt = 0; nt < 4; nt++)
#pragma unroll
            for (int q = 0; q < 4; q++) acc[mt][nt][q] = 0.0f;

    int ar  = tid >> 3;
    int ac4 = tid & 7;
    int bkr = tid >> 5;
    int bc4 = tid & 31;

    for (int k0 = 0; k0 < DIMK; k0 += 32) {
#pragma unroll
        for (int j = 0; j < 4; j++) {
            int row  = ar + 32 * j;
            int grow = rowBase + row;
            float4 v = make_float4(0.f, 0.f, 0.f, 0.f);
            if (grow < N)
                v = *reinterpret_cast<const float4*>(&A[(size_t)grow * DIMK + k0 + ac4 * 4]);
            v.x = to_tf32(v.x); v.y = to_tf32(v.y);
            v.z = to_tf32(v.z); v.w = to_tf32(v.w);
            *reinterpret_cast<float4*>(&As[row * 36 + ac4 * 4]) = v;
        }
#pragma unroll
        for (int j = 0; j < 4; j++) {
            int k = bkr + 8 * j;
            float4 v = *reinterpret_cast<const float4*>(
                &B[(size_t)(k0 + k) * DIMOUT + colBase + bc4 * 4]);
            v.x = to_tf32(v.x); v.y = to_tf32(v.y);
            v.z = to_tf32(v.z); v.w = to_tf32(v.w);
            *reinterpret_cast<float4*>(&Bs[k * 136 + bc4 * 4]) = v;
        }
        __syncthreads();

#pragma unroll
        for (int kk = 0; kk < 32; kk += 8) {
            uint32_t afr[4][4];
            uint32_t bfr[4][2];
#pragma unroll
            for (int mt = 0; mt < 4; mt++) {
                int rb = wm * 64 + mt * 16;
                afr[mt][0] = __float_as_uint(As[(rb + g)     * 36 + kk + c]);
                afr[mt][1] = __float_as_uint(As[(rb + g + 8) * 36 + kk + c]);
                afr[mt][2] = __float_as_uint(As[(rb + g)     * 36 + kk + c + 4]);
                afr[mt][3] = __float_as_uint(As[(rb + g + 8) * 36 + kk + c + 4]);
            }
#pragma unroll
            for (int nt = 0; nt < 4; nt++) {
                int nb = wn * 32 + nt * 8;
                bfr[nt][0] = __float_as_uint(Bs[(kk + c)     * 136 + nb + g]);
                bfr[nt][1] = __float_as_uint(Bs[(kk + c + 4) * 136 + nb + g]);
            }
#pragma unroll
            for (int mt = 0; mt < 4; mt++)
#pragma unroll
                for (int nt = 0; nt < 4; nt++)
                    mma_tf32(acc[mt][nt], afr[mt], bfr[nt]);
        }
        __syncthreads();
    }

    // epilogue: convert to fp16, 4-byte __half2 stores
#pragma unroll
    for (int mt = 0; mt < 4; mt++) {
        int row = rowBase + wm * 64 + mt * 16 + g;
#pragma unroll
        for (int nt = 0; nt < 4; nt++) {
            int col = colBase + wn * 32 + nt * 8 + 2 * c;
            if (row < N)
                *reinterpret_cast<__half2*>(&C[(size_t)row * DIMOUT + col]) =
                    __floats2half2_rn(acc[mt][nt][0], acc[mt][nt][1]);
            if (row + 8 < N)
                *reinterpret_cast<__half2*>(&C[(size_t)(row + 8) * DIMOUT + col]) =
                    __floats2half2_rn(acc[mt][nt][2], acc[mt][nt][3]);
        }
    }
}

// ---------------------------------------------------------------------------
// K6: CSR gather (atomic-free), fp16 xw, precomputed edge weights
//   out[i,:] = tb + dinv[i]^2 * xw[i,:] + sum_e w_e * xw[src_e,:]
// block = 128 threads, each owns 4 output columns (one uint2 = 4 halves)
// ---------------------------------------------------------------------------
__global__ __launch_bounds__(128) void k_gather(const int* __restrict__ rowstart,
                                                const int2* __restrict__ csr_sw,
                                                const __half* __restrict__ xw,
                                                const float* __restrict__ dinv,
                                                const float* __restrict__ tb,
                                                float* __restrict__ out, int N) {
    int i = blockIdx.x;
    int t = threadIdx.x;
    int start = rowstart[i];
    int end   = rowstart[i + 1];
    float di  = dinv[i];

    float4 acc = *(reinterpret_cast<const float4*>(tb) + t);

    // self loop (weight dinv^2)
    {
        uint2 raw = __ldg(reinterpret_cast<const uint2*>(xw + (size_t)i * DIMOUT) + t);
        float2 f0 = __half22float2(*reinterpret_cast<__half2*>(&raw.x));
        float2 f1 = __half22float2(*reinterpret_cast<__half2*>(&raw.y));
        float w = di * di;
        acc.x += w * f0.x;
        acc.y += w * f0.y;
        acc.z += w * f1.x;
        acc.w += w * f1.y;
    }

    for (int j = start; j < end; j++) {
        int2 sw = __ldg(&csr_sw[j]);
        int s   = sw.x;
        float w = __int_as_float(sw.y);
        uint2 raw = __ldg(reinterpret_cast<const uint2*>(xw + (size_t)s * DIMOUT) + t);
        float2 f0 = __half22float2(*reinterpret_cast<__half2*>(&raw.x));
        float2 f1 = __half22float2(*reinterpret_cast<__half2*>(&raw.y));
        acc.x += w * f0.x;
        acc.y += w * f0.y;
        acc.z += w * f1.x;
        acc.w += w * f1.y;
    }
    *(reinterpret_cast<float4*>(out + (size_t)i * DIMOUT) + t) = acc;
}

// ---------------------------------------------------------------------------
// launch
// ---------------------------------------------------------------------------
extern "C" void kernel_launch(void* const* d_in, const int* in_sizes, int n_in,
                              void* d_out, int out_size) {
    const float* x    = (const float*)d_in[0];
    const float* temb = (const float*)d_in[1];
    const int*   ei   = (const int*)d_in[2];   // int32 (JAX x64 disabled)
    const float* W    = (const float*)d_in[3];
    const float* b    = (const float*)d_in[4];
    const float* Wt   = (const float*)d_in[5];
    const float* bt   = (const float*)d_in[6];
    float*       out  = (float*)d_out;

    int N = in_sizes[0] / DIMK;
    int E = in_sizes[2] / 2;

    __half* xw;   cudaGetSymbolAddress((void**)&xw,    g_xw);
    float* dinv;  cudaGetSymbolAddress((void**)&dinv,  g_dinv);
    float* tb;    cudaGetSymbolAddress((void**)&tb,    g_tb);
    int* count;   cudaGetSymbolAddress((void**)&count, g_count);
    int* rowst;   cudaGetSymbolAddress((void**)&rowst, g_rowstart);
    int* cursor;  cudaGetSymbolAddress((void**)&cursor,g_cursor);
    int2* csrsw;  cudaGetSymbolAddress((void**)&csrsw, g_csr_sw);

    int zeroBlocks = (N + 255) / 256;
    k_setup<<<16 + zeroBlocks, 256>>>(temb, Wt, b, bt, tb, count, N);
    k_count_edges<<<(E + 255) / 256, 256>>>(ei, count, E);
    k_scan<<<1, 1024>>>(count, rowst, cursor, dinv, N);
    k_fill<<<(E + 255) / 256, 256>>>(ei, cursor, dinv, csrsw, E);

    dim3 gg(DIMOUT / 128, (N + 127) / 128);
    k_gemm_tf32<<<gg, 256>>>(x, W, xw, N);

    k_gather<<<N, 128>>>(rowst, csrsw, xw, dinv, tb, out, N);
}

// round 12
// speedup vs baseline: 1.0777x; 1.0203x over previous
#include <cuda_runtime.h>
#include <cuda_fp16.h>
#include <cstdint>

// Problem shape (fixed by the dataset): N=10000, E=160000, IN=OUT=512, TC=256.
#define MAXN   10240
#define MAXE   163840
#define DIMK   512
#define DIMOUT 512
#define DIMTC  256

// Static device scratch (no runtime allocation allowed).
__device__ __half g_xw[MAXN * DIMOUT];  // x @ W  (fp16 gather traffic)
__device__ float  g_dinv[MAXN];         // rsqrt(deg)
__device__ float  g_tb[DIMOUT];         // b + bt + t_emb @ Wt
__device__ int    g_count[MAXN];        // in-degree (excl self loop)
__device__ int    g_rowstart[MAXN + 1]; // CSR row offsets
__device__ int    g_cursor[MAXN];       // fill cursors
__device__ int2   g_csr_sw[MAXE];       // {src, weight_bits} per CSR slot

// ---------------------------------------------------------------------------
// helpers
// ---------------------------------------------------------------------------
__device__ __forceinline__ float to_tf32(float x) {
    uint32_t u;
    asm("cvt.rna.tf32.f32 %0, %1;" : "=r"(u) : "f"(x));
    return __uint_as_float(u);
}

__device__ __forceinline__ void mma_tf32(float* d, const uint32_t* a, const uint32_t* b) {
    asm volatile(
        "mma.sync.aligned.m16n8k8.row.col.f32.tf32.tf32.f32 "
        "{%0,%1,%2,%3}, {%4,%5,%6,%7}, {%8,%9}, {%0,%1,%2,%3};"
        : "+f"(d[0]), "+f"(d[1]), "+f"(d[2]), "+f"(d[3])
        : "r"(a[0]), "r"(a[1]), "r"(a[2]), "r"(a[3]),
          "r"(b[0]), "r"(b[1]));
}

// ---------------------------------------------------------------------------
// K1 (fused): blocks [0,16): tb[j] = b[j]+bt[j]+sum_k t_emb[k]*Wt[k,j]
//             blocks [16,...): count[i] = 0
// ---------------------------------------------------------------------------
__global__ void k_setup(const float* __restrict__ t_emb,
                        const float* __restrict__ Wt,
                        const float* __restrict__ b,
                        const float* __restrict__ bt,
                        float* __restrict__ tb,
                        int* __restrict__ count, int N) {
    if (blockIdx.x < 16) {
        __shared__ float red[8][32];
        int jloc = threadIdx.x & 31;
        int kc   = threadIdx.x >> 5;
        int j    = blockIdx.x * 32 + jloc;
        float acc = 0.0f;
        int k0 = kc * 32;
#pragma unroll
        for (int k = 0; k < 32; k++) {
            acc += t_emb[k0 + k] * Wt[(k0 + k) * DIMOUT + j];
        }
        red[kc][jloc] = acc;
        __syncthreads();
        if (kc == 0) {
            float s = b[j] + bt[j];
#pragma unroll
            for (int q = 0; q < 8; q++) s += red[q][jloc];
            tb[j] = s;
        }
    } else {
        int i = (blockIdx.x - 16) * blockDim.x + threadIdx.x;
        if (i < N) count[i] = 0;
    }
}

// ---------------------------------------------------------------------------
// K2 (fused): blocks [0,gemmBlocks): TF32 GEMM  C = A @ B  (fp16 out)
//             blocks [gemmBlocks,...): dst histogram (independent work,
//             hidden under the GEMM instead of a separate serialized launch)
// ---------------------------------------------------------------------------
__global__ __launch_bounds__(256, 2)
void k_gemm_count(const float* __restrict__ A,
                  const float* __restrict__ B,
                  __half* __restrict__ C, int N, int gemmBlocks,
                  const int* __restrict__ ei, int* __restrict__ count, int E) {
    if ((int)blockIdx.x >= gemmBlocks) {
        int base = ((int)blockIdx.x - gemmBlocks) * 1024 + threadIdx.x;
#pragma unroll
        for (int q = 0; q < 4; q++) {
            int e = base + q * 256;
            if (e < E) atomicAdd(&count[ei[E + e]], 1);
        }
        return;
    }

    __shared__ float As[128 * 36];
    __shared__ float Bs[32 * 136];

    int tid  = threadIdx.x;
    int lane = tid & 31;
    int wid  = tid >> 5;
    int wm   = wid & 1;
    int wn   = wid >> 1;
    int g    = lane >> 2;
    int c    = lane & 3;

    int rowBase = ((int)blockIdx.x >> 2) * 128;
    int colBase = ((int)blockIdx.x & 3) * 128;

    float acc[4][4][4];
#pragma unroll
    for (int mt = 0; mt < 4; mt++)
#pragma unroll
        for (int nt = 0; nt < 4; nt++)
#pragma unroll
            for (int q = 0; q < 4; q++) acc[mt][nt][q] = 0.0f;

    int ar  = tid >> 3;
    int ac4 = tid & 7;
    int bkr = tid >> 5;
    int bc4 = tid & 31;

    for (int k0 = 0; k0 < DIMK; k0 += 32) {
#pragma unroll
        for (int j = 0; j < 4; j++) {
            int row  = ar + 32 * j;
            int grow = rowBase + row;
            float4 v = make_float4(0.f, 0.f, 0.f, 0.f);
            if (grow < N)
                v = *reinterpret_cast<const float4*>(&A[(size_t)grow * DIMK + k0 + ac4 * 4]);
            v.x = to_tf32(v.x); v.y = to_tf32(v.y);
            v.z = to_tf32(v.z); v.w = to_tf32(v.w);
            *reinterpret_cast<float4*>(&As[row * 36 + ac4 * 4]) = v;
        }
#pragma unroll
        for (int j = 0; j < 4; j++) {
            int k = bkr + 8 * j;
            float4 v = *reinterpret_cast<const float4*>(
                &B[(size_t)(k0 + k) * DIMOUT + colBase + bc4 * 4]);
            v.x = to_tf32(v.x); v.y = to_tf32(v.y);
            v.z = to_tf32(v.z); v.w = to_tf32(v.w);
            *reinterpret_cast<float4*>(&Bs[k * 136 + bc4 * 4]) = v;
        }
        __syncthreads();

#pragma unroll
        for (int kk = 0; kk < 32; kk += 8) {
            uint32_t afr[4][4];
            uint32_t bfr[4][2];
#pragma unroll
            for (int mt = 0; mt < 4; mt++) {
                int rb = wm * 64 + mt * 16;
                afr[mt][0] = __float_as_uint(As[(rb + g)     * 36 + kk + c]);
                afr[mt][1] = __float_as_uint(As[(rb + g + 8) * 36 + kk + c]);
                afr[mt][2] = __float_as_uint(As[(rb + g)     * 36 + kk + c + 4]);
                afr[mt][3] = __float_as_uint(As[(rb + g + 8) * 36 + kk + c + 4]);
            }
#pragma unroll
            for (int nt = 0; nt < 4; nt++) {
                int nb = wn * 32 + nt * 8;
                bfr[nt][0] = __float_as_uint(Bs[(kk + c)     * 136 + nb + g]);
                bfr[nt][1] = __float_as_uint(Bs[(kk + c + 4) * 136 + nb + g]);
            }
#pragma unroll
            for (int mt = 0; mt < 4; mt++)
#pragma unroll
                for (int nt = 0; nt < 4; nt++)
                    mma_tf32(acc[mt][nt], afr[mt], bfr[nt]);
        }
        __syncthreads();
    }

#pragma unroll
    for (int mt = 0; mt < 4; mt++) {
        int row = rowBase + wm * 64 + mt * 16 + g;
#pragma unroll
        for (int nt = 0; nt < 4; nt++) {
            int col = colBase + wn * 32 + nt * 8 + 2 * c;
            if (row < N)
                *reinterpret_cast<__half2*>(&C[(size_t)row * DIMOUT + col]) =
                    __floats2half2_rn(acc[mt][nt][0], acc[mt][nt][1]);
            if (row + 8 < N)
                *reinterpret_cast<__half2*>(&C[(size_t)(row + 8) * DIMOUT + col]) =
                    __floats2half2_rn(acc[mt][nt][2], acc[mt][nt][3]);
        }
    }
}

// ---------------------------------------------------------------------------
// K3: exclusive scan of count -> rowstart[0..N] + cursor copy + dinv
// ---------------------------------------------------------------------------
__global__ __launch_bounds__(1024) void k_scan(const int* __restrict__ count,
                                               int* __restrict__ rowstart,
                                               int* __restrict__ cursor,
                                               float* __restrict__ dinv, int N) {
    __shared__ int part[1024];
    int tid = threadIdx.x;
    int PER = (N + 1023) >> 10;
    int base = tid * PER;
    int s = 0;
    for (int q = 0; q < PER; q++) {
        int idx = base + q;
        s += (idx < N) ? count[idx] : 0;
    }
    part[tid] = s;
    __syncthreads();
    for (int off = 1; off < 1024; off <<= 1) {
        int v = (tid >= off) ? part[tid - off] : 0;
        __syncthreads();
        part[tid] += v;
        __syncthreads();
    }
    int run = (tid > 0) ? part[tid - 1] : 0;
    for (int q = 0; q < PER; q++) {
        int idx = base + q;
        if (idx <= N) {
            rowstart[idx] = run;
            if (idx < N) cursor[idx] = run;
        }
        if (idx < N) {
            int c = count[idx];
            dinv[idx] = rsqrtf((float)c + 1.0f);
            run += c;
        }
    }
}

// ---------------------------------------------------------------------------
// K4: CSR fill: csr_sw[pos] = {src, dinv[src]*dinv[dst]}, pos = cursor[dst]++
// ---------------------------------------------------------------------------
__global__ void k_fill(const int* __restrict__ ei, int* cursor,
                       const float* __restrict__ dinv,
                       int2* __restrict__ csr_sw, int E) {
    int e = blockIdx.x * blockDim.x + threadIdx.x;
    if (e < E) {
        int s = ei[e];
        int d = ei[E + e];
        float w = dinv[s] * dinv[d];
        int pos = atomicAdd(&cursor[d], 1);
        csr_sw[pos] = make_int2(s, __float_as_int(w));
    }
}

// ---------------------------------------------------------------------------
// K5: CSR gather (atomic-free), fp16 xw, precomputed edge weights
// ---------------------------------------------------------------------------
__global__ __launch_bounds__(128) void k_gather(const int* __restrict__ rowstart,
                                                const int2* __restrict__ csr_sw,
                                                const __half* __restrict__ xw,
                                                const float* __restrict__ dinv,
                                                const float* __restrict__ tb,
                                                float* __restrict__ out, int N) {
    int i = blockIdx.x;
    int t = threadIdx.x;
    int start = rowstart[i];
    int end   = rowstart[i + 1];
    float di  = dinv[i];

    float4 acc = *(reinterpret_cast<const float4*>(tb) + t);

    {
        uint2 raw = __ldg(reinterpret_cast<const uint2*>(xw + (size_t)i * DIMOUT) + t);
        float2 f0 = __half22float2(*reinterpret_cast<__half2*>(&raw.x));
        float2 f1 = __half22float2(*reinterpret_cast<__half2*>(&raw.y));
        float w = di * di;
        acc.x += w * f0.x;
        acc.y += w * f0.y;
        acc.z += w * f1.x;
        acc.w += w * f1.y;
    }

    for (int j = start; j < end; j++) {
        int2 sw = __ldg(&csr_sw[j]);
        int s   = sw.x;
        float w = __int_as_float(sw.y);
        uint2 raw = __ldg(reinterpret_cast<const uint2*>(xw + (size_t)s * DIMOUT) + t);
        float2 f0 = __half22float2(*reinterpret_cast<__half2*>(&raw.x));
        float2 f1 = __half22float2(*reinterpret_cast<__half2*>(&raw.y));
        acc.x += w * f0.x;
        acc.y += w * f0.y;
        acc.z += w * f1.x;
        acc.w += w * f1.y;
    }
    *(reinterpret_cast<float4*>(out + (size_t)i * DIMOUT) + t) = acc;
}

// ---------------------------------------------------------------------------
// launch
// ---------------------------------------------------------------------------
extern "C" void kernel_launch(void* const* d_in, const int* in_sizes, int n_in,
                              void* d_out, int out_size) {
    const float* x    = (const float*)d_in[0];
    const float* temb = (const float*)d_in[1];
    const int*   ei   = (const int*)d_in[2];   // int32 (JAX x64 disabled)
    const float* W    = (const float*)d_in[3];
    const float* b    = (const float*)d_in[4];
    const float* Wt   = (const float*)d_in[5];
    const float* bt   = (const float*)d_in[6];
    float*       out  = (float*)d_out;

    int N = in_sizes[0] / DIMK;
    int E = in_sizes[2] / 2;

    __half* xw;   cudaGetSymbolAddress((void**)&xw,    g_xw);
    float* dinv;  cudaGetSymbolAddress((void**)&dinv,  g_dinv);
    float* tb;    cudaGetSymbolAddress((void**)&tb,    g_tb);
    int* count;   cudaGetSymbolAddress((void**)&count, g_count);
    int* rowst;   cudaGetSymbolAddress((void**)&rowst, g_rowstart);
    int* cursor;  cudaGetSymbolAddress((void**)&cursor,g_cursor);
    int2* csrsw;  cudaGetSymbolAddress((void**)&csrsw, g_csr_sw);

    int zeroBlocks = (N + 255) / 256;
    k_setup<<<16 + zeroBlocks, 256>>>(temb, Wt, b, bt, tb, count, N);

    int gemmBlocks  = 4 * ((N + 127) / 128);
    int countBlocks = (E + 1023) / 1024;
    k_gemm_count<<<gemmBlocks + countBlocks, 256>>>(x, W, xw, N, gemmBlocks,
                                                    ei, count, E);

    k_scan<<<1, 1024>>>(count, rowst, cursor, dinv, N);
    k_fill<<<(E + 255) / 256, 256>>>(ei, cursor, dinv, csrsw, E);

    k_gather<<<N, 128>>>(rowst, csrsw, xw, dinv, tb, out, N);
}